// round 2
// baseline (speedup 1.0000x reference)
#include <cuda_runtime.h>
#include <cstdint>

// Problem constants
#define NB      32
#define CDIM    256
#define HWN     4096
#define KCODES  1024
#define N_VEC   (NB * HWN)        // 131072
#define N_ZQ    (NB * CDIM * HWN) // 33554432

// Tiling
#define BM 128   // vectors per block
#define BN 64    // codes per n-tile
#define KC 32    // k-chunk

// Static device scratch (no allocations allowed)
__device__ float  g_et[CDIM * KCODES];  // transposed codebook [k][n]
__device__ float  g_se[KCODES];         // ||e_k||^2 (fp32)
__device__ float  g_sz[N_VEC];          // ||z_m||^2 (fp32, XLA-order hypothesis H0)
__device__ int    g_idx[N_VEC];
__device__ double g_loss;

// ---------------------------------------------------------------------------
// Prep: transpose codebook to [k][n], compute ||e||^2, zero loss accum.
// (||e||^2 ~ 8.5e-5; any fp32 order is bit-safe at the 3e-5 dist quantum.)
// ---------------------------------------------------------------------------
__global__ void prep_kernel(const float* __restrict__ cb) {
    int n = blockIdx.x;       // code id 0..1023
    int t = threadIdx.x;      // dim   0..255
    float v = cb[n * CDIM + t];
    g_et[t * KCODES + n] = v;
    __shared__ float red[256];
    red[t] = __fmul_rn(v, v);
    __syncthreads();
    for (int s = 128; s > 0; s >>= 1) {
        if (t < s) red[t] = __fadd_rn(red[t], red[t + s]);
        __syncthreads();
    }
    if (t == 0) {
        g_se[n] = red[0];
        if (n == 0) g_loss = 0.0;
    }
}

// ---------------------------------------------------------------------------
// S_z kernel — hypothesis H0: XLA column-reduction = one serial ascending
// fp32 chain per vector, mul and add NOT contracted to FMA.
// Lanes map to consecutive hw -> fully coalesced loads.
// ---------------------------------------------------------------------------
__global__ void sz_kernel(const float* __restrict__ z) {
    int v  = blockIdx.x * blockDim.x + threadIdx.x;  // 0..131071
    int b  = v >> 12;
    int hw = v & (HWN - 1);
    const float* p = z + (size_t)b * CDIM * HWN + hw;
    float acc = 0.0f;
#pragma unroll 8
    for (int c = 0; c < CDIM; c++) {
        float x = __ldg(p + (size_t)c * HWN);
        acc = __fadd_rn(acc, __fmul_rn(x, x));   // serial ascending, no FMA
    }
    g_sz[v] = acc;
}

// ---------------------------------------------------------------------------
// Main kernel: fp32 GEMM-style dot with packed f32x2 FMA.
// Per output element the accumulation is a single serial ascending-k fp32
// FMA chain — matching cuBLAS SGEMM's per-element order (bitwise).
// Epilogue replicates the reference exactly:
//   d = fl( fl(S_z + S_e) - 2*dot ),  argmin with first-index ties.
// ---------------------------------------------------------------------------
__device__ __forceinline__ unsigned long long dup2(float x) {
    unsigned long long r;
    unsigned u = __float_as_uint(x);
    asm("mov.b64 %0, {%1, %2};" : "=l"(r) : "r"(u), "r"(u));
    return r;
}
#define FMA2(acc, a, b) \
    asm("fma.rn.f32x2 %0, %1, %2, %0;" : "+l"(acc) : "l"(a), "l"(b))

__global__ void __launch_bounds__(256, 1)
vq_argmin_kernel(const float* __restrict__ z) {
    extern __shared__ float smem[];
    float* z_s = smem;               // [CDIM][BM]  = 128 KB
    float* e_s = smem + CDIM * BM;   // [KC][BN]    = 8 KB

    const int tid = threadIdx.x;
    const int tx = tid & 15;         // 0..15 -> n group
    const int ty = tid >> 4;         // 0..15 -> m group
    const int m0 = blockIdx.x * BM;  // global vector base
    const int b   = m0 >> 12;
    const int hw0 = m0 & (HWN - 1);

    // Load z tile: z[(b*256 + c)*4096 + hw0 + m]  -> z_s[c][m]
    for (int i = tid; i < (CDIM * BM) / 4; i += 256) {
        int c  = i >> 5;
        int mq = i & 31;
        float4 v = *(const float4*)(z + (((size_t)b * CDIM + c) << 12) + hw0 + (mq << 2));
        *(float4*)(z_s + c * BM + (mq << 2)) = v;
    }

    // Per-thread running argmin over its 8 m-rows.
    float szr[8];
#pragma unroll
    for (int i = 0; i < 8; i++) szr[i] = g_sz[m0 + (ty << 3) + i];

    float bestd[8];
    int   besti[8];
#pragma unroll
    for (int i = 0; i < 8; i++) { bestd[i] = 3.4e38f; besti[i] = 0; }

    for (int nt = 0; nt < KCODES / BN; nt++) {
        unsigned long long acc[16];
#pragma unroll
        for (int i = 0; i < 16; i++) acc[i] = 0ull;  // (0.0f, 0.0f)

        for (int kc = 0; kc < CDIM / KC; kc++) {
            __syncthreads();  // protect e_s from previous readers
#pragma unroll
            for (int i = 0; i < 2; i++) {
                int li   = tid + i * 256;
                int r    = li >> 4;
                int colq = (li & 15) << 2;
                *(float4*)(e_s + r * BN + colq) =
                    *(const float4*)(g_et + (kc * KC + r) * KCODES + nt * BN + colq);
            }
            __syncthreads();

#pragma unroll
            for (int k = 0; k < KC; k++) {
                const float* zr = z_s + (kc * KC + k) * BM + (ty << 3);
                ulonglong2 A0 = *(const ulonglong2*)(zr);      // m {0,1},{2,3}
                ulonglong2 A1 = *(const ulonglong2*)(zr + 4);  // m {4,5},{6,7}
                float4 bq = *(const float4*)(e_s + k * BN + (tx << 2));
                unsigned long long b0 = dup2(bq.x);
                unsigned long long b1 = dup2(bq.y);
                unsigned long long b2 = dup2(bq.z);
                unsigned long long b3 = dup2(bq.w);
                FMA2(acc[ 0], A0.x, b0); FMA2(acc[ 1], A0.x, b1);
                FMA2(acc[ 2], A0.x, b2); FMA2(acc[ 3], A0.x, b3);
                FMA2(acc[ 4], A0.y, b0); FMA2(acc[ 5], A0.y, b1);
                FMA2(acc[ 6], A0.y, b2); FMA2(acc[ 7], A0.y, b3);
                FMA2(acc[ 8], A1.x, b0); FMA2(acc[ 9], A1.x, b1);
                FMA2(acc[10], A1.x, b2); FMA2(acc[11], A1.x, b3);
                FMA2(acc[12], A1.y, b0); FMA2(acc[13], A1.y, b1);
                FMA2(acc[14], A1.y, b2); FMA2(acc[15], A1.y, b3);
            }
        }

        // Epilogue: d = fl( fl(S_z + S_e) - 2*dot ), running first-index argmin.
        const int nb = nt * BN + (tx << 2);
#pragma unroll
        for (int j = 0; j < 4; j++) {
            float se = g_se[nb + j];
#pragma unroll
            for (int mp = 0; mp < 4; mp++) {
                unsigned long long p = acc[mp * 4 + j];
                float dlo = __uint_as_float((unsigned)(p & 0xffffffffu));
                float dhi = __uint_as_float((unsigned)(p >> 32));
                int m = mp * 2;
                float d0 = __fsub_rn(__fadd_rn(szr[m],     se), __fmul_rn(2.0f, dlo));
                float d1 = __fsub_rn(__fadd_rn(szr[m + 1], se), __fmul_rn(2.0f, dhi));
                if (d0 < bestd[m])     { bestd[m]     = d0; besti[m]     = nb + j; }
                if (d1 < bestd[m + 1]) { bestd[m + 1] = d1; besti[m + 1] = nb + j; }
            }
        }
    }

    // Cross-thread reduction: 16 tx partials per vector row, ties -> min index.
    __syncthreads();
    float* rv = smem;                        // [BM][16] floats
    int*   ri = (int*)(smem + BM * 16);      // [BM][16] ints
#pragma unroll
    for (int i = 0; i < 8; i++) {
        int m = (ty << 3) + i;
        rv[m * 16 + tx] = bestd[i];
        ri[m * 16 + tx] = besti[i];
    }
    __syncthreads();
    if (tid < BM) {
        float bv = rv[tid * 16];
        int   bi = ri[tid * 16];
#pragma unroll
        for (int t = 1; t < 16; t++) {
            float v  = rv[tid * 16 + t];
            int   ix = ri[tid * 16 + t];
            if (v < bv || (v == bv && ix < bi)) { bv = v; bi = ix; }
        }
        g_idx[m0 + tid] = bi;
    }
}

// ---------------------------------------------------------------------------
// Gather + straight-through + loss accumulation (+ indices as float).
// z_q = z + (e - z) with explicit fp32 ops to match the reference bitwise.
// ---------------------------------------------------------------------------
__global__ void gather_kernel(const float* __restrict__ z,
                              const float* __restrict__ cb,
                              float* __restrict__ out, int mode) {
    int v  = blockIdx.x * blockDim.x + threadIdx.x;  // 0..131071
    int b  = v >> 12;
    int hw = v & (HWN - 1);
    int idx = g_idx[v];
    const float4* crow = (const float4*)(cb + idx * CDIM);

    float lsum = 0.0f;
    for (int cc = 0; cc < CDIM / 8; cc++) {
        float4 e0 = crow[cc * 2];
        float4 e1 = crow[cc * 2 + 1];
        float er[8] = {e0.x, e0.y, e0.z, e0.w, e1.x, e1.y, e1.z, e1.w};
#pragma unroll
        for (int j = 0; j < 8; j++) {
            int c  = cc * 8 + j;
            size_t zi = (((size_t)b * CDIM + c) << 12) + hw;  // coalesced over hw
            float zv = z[zi];
            float t  = __fsub_rn(er[j], zv);          // e - z
            out[zi]  = __fadd_rn(zv, t);              // z + (e - z)
            lsum = __fmaf_rn(t, t, lsum);
        }
    }
    for (int o = 16; o > 0; o >>= 1)
        lsum += __shfl_down_sync(0xffffffffu, lsum, o);
    if ((threadIdx.x & 31) == 0) atomicAdd(&g_loss, (double)lsum);

    if (mode >= 2) out[N_ZQ + 2 + v] = (float)idx;
}

__global__ void finalize_kernel(float* __restrict__ out, int mode) {
    if (mode >= 1) {
        float mean = (float)(g_loss / (double)N_ZQ);
        out[N_ZQ]     = mean;          // codebook_loss
        out[N_ZQ + 1] = 0.25f * mean;  // commitment_loss = exactly 0.25 * mean
    }
}

// ---------------------------------------------------------------------------
extern "C" void kernel_launch(void* const* d_in, const int* in_sizes, int n_in,
                              void* d_out, int out_size) {
    const float* z  = (const float*)d_in[0];
    const float* cb = (const float*)d_in[1];
    float* out = (float*)d_out;

    int mode = 0;
    if (out_size >= N_ZQ + 2) mode = 1;
    if (out_size >= N_ZQ + 2 + N_VEC) mode = 2;

    const size_t SMEM = (size_t)(CDIM * BM + KC * BN) * sizeof(float); // 139264 B
    cudaFuncSetAttribute(vq_argmin_kernel,
                         cudaFuncAttributeMaxDynamicSharedMemorySize, (int)SMEM);

    prep_kernel<<<KCODES, 256>>>(cb);
    sz_kernel<<<N_VEC / 256, 256>>>(z);
    vq_argmin_kernel<<<N_VEC / BM, 256, SMEM>>>(z);
    gather_kernel<<<N_VEC / 256, 256>>>(z, cb, out, mode);
    finalize_kernel<<<1, 1>>>(out, mode);
}

// round 3
// speedup vs baseline: 1.0000x; 1.0000x over previous
#include <cuda_runtime.h>
#include <cstdint>

// Problem constants
#define NB      32
#define CDIM    256
#define HWN     4096
#define KCODES  1024
#define N_VEC   (NB * HWN)        // 131072
#define N_ZQ    (NB * CDIM * HWN) // 33554432

// Tiling
#define BM 128   // vectors per block
#define BN 64    // codes per n-tile
#define KC 32    // k-chunk

// Static device scratch (no allocations allowed)
__device__ float  g_et[CDIM * KCODES];  // transposed codebook [k][n]
__device__ float  g_se[KCODES];         // ||e_k||^2 (fp32)
__device__ float  g_sz[N_VEC];          // ||z_m||^2 (fp32, XLA-order hypothesis H0)
__device__ int    g_idx[N_VEC];
__device__ double g_loss;

// ---------------------------------------------------------------------------
// Prep: transpose codebook to [k][n], compute ||e||^2, zero loss accum.
// (||e||^2 ~ 8.5e-5; any fp32 order is bit-safe at the 3e-5 dist quantum.)
// ---------------------------------------------------------------------------
__global__ void prep_kernel(const float* __restrict__ cb) {
    int n = blockIdx.x;       // code id 0..1023
    int t = threadIdx.x;      // dim   0..255
    float v = cb[n * CDIM + t];
    g_et[t * KCODES + n] = v;
    __shared__ float red[256];
    red[t] = __fmul_rn(v, v);
    __syncthreads();
    for (int s = 128; s > 0; s >>= 1) {
        if (t < s) red[t] = __fadd_rn(red[t], red[t + s]);
        __syncthreads();
    }
    if (t == 0) {
        g_se[n] = red[0];
        if (n == 0) g_loss = 0.0;
    }
}

// ---------------------------------------------------------------------------
// S_z kernel — hypothesis H0: XLA column-reduction = one serial ascending
// fp32 chain per vector, mul and add NOT contracted to FMA.
// Lanes map to consecutive hw -> fully coalesced loads.
// ---------------------------------------------------------------------------
__global__ void sz_kernel(const float* __restrict__ z) {
    int v  = blockIdx.x * blockDim.x + threadIdx.x;  // 0..131071
    int b  = v >> 12;
    int hw = v & (HWN - 1);
    const float* p = z + (size_t)b * CDIM * HWN + hw;
    float acc = 0.0f;
#pragma unroll 8
    for (int c = 0; c < CDIM; c++) {
        float x = __ldg(p + (size_t)c * HWN);
        acc = __fadd_rn(acc, __fmul_rn(x, x));   // serial ascending, no FMA
    }
    g_sz[v] = acc;
}

// ---------------------------------------------------------------------------
// Main kernel: fp32 GEMM-style dot with packed f32x2 FMA.
// Per output element the accumulation is a single serial ascending-k fp32
// FMA chain — matching cuBLAS SGEMM's per-element order (bitwise).
// Epilogue replicates the reference exactly:
//   d = fl( fl(S_z + S_e) - 2*dot ),  argmin with first-index ties.
// ---------------------------------------------------------------------------
__device__ __forceinline__ unsigned long long dup2(float x) {
    unsigned long long r;
    unsigned u = __float_as_uint(x);
    asm("mov.b64 %0, {%1, %2};" : "=l"(r) : "r"(u), "r"(u));
    return r;
}
#define FMA2(acc, a, b) \
    asm("fma.rn.f32x2 %0, %1, %2, %0;" : "+l"(acc) : "l"(a), "l"(b))

__global__ void __launch_bounds__(256, 1)
vq_argmin_kernel(const float* __restrict__ z) {
    extern __shared__ float smem[];
    float* z_s = smem;               // [CDIM][BM]  = 128 KB
    float* e_s = smem + CDIM * BM;   // [KC][BN]    = 8 KB

    const int tid = threadIdx.x;
    const int tx = tid & 15;         // 0..15 -> n group
    const int ty = tid >> 4;         // 0..15 -> m group
    const int m0 = blockIdx.x * BM;  // global vector base
    const int b   = m0 >> 12;
    const int hw0 = m0 & (HWN - 1);

    // Load z tile: z[(b*256 + c)*4096 + hw0 + m]  -> z_s[c][m]
    for (int i = tid; i < (CDIM * BM) / 4; i += 256) {
        int c  = i >> 5;
        int mq = i & 31;
        float4 v = *(const float4*)(z + (((size_t)b * CDIM + c) << 12) + hw0 + (mq << 2));
        *(float4*)(z_s + c * BM + (mq << 2)) = v;
    }

    // Per-thread running argmin over its 8 m-rows.
    float szr[8];
#pragma unroll
    for (int i = 0; i < 8; i++) szr[i] = g_sz[m0 + (ty << 3) + i];

    float bestd[8];
    int   besti[8];
#pragma unroll
    for (int i = 0; i < 8; i++) { bestd[i] = 3.4e38f; besti[i] = 0; }

    for (int nt = 0; nt < KCODES / BN; nt++) {
        unsigned long long acc[16];
#pragma unroll
        for (int i = 0; i < 16; i++) acc[i] = 0ull;  // (0.0f, 0.0f)

        for (int kc = 0; kc < CDIM / KC; kc++) {
            __syncthreads();  // protect e_s from previous readers
#pragma unroll
            for (int i = 0; i < 2; i++) {
                int li   = tid + i * 256;
                int r    = li >> 4;
                int colq = (li & 15) << 2;
                *(float4*)(e_s + r * BN + colq) =
                    *(const float4*)(g_et + (kc * KC + r) * KCODES + nt * BN + colq);
            }
            __syncthreads();

#pragma unroll
            for (int k = 0; k < KC; k++) {
                const float* zr = z_s + (kc * KC + k) * BM + (ty << 3);
                ulonglong2 A0 = *(const ulonglong2*)(zr);      // m {0,1},{2,3}
                ulonglong2 A1 = *(const ulonglong2*)(zr + 4);  // m {4,5},{6,7}
                float4 bq = *(const float4*)(e_s + k * BN + (tx << 2));
                unsigned long long b0 = dup2(bq.x);
                unsigned long long b1 = dup2(bq.y);
                unsigned long long b2 = dup2(bq.z);
                unsigned long long b3 = dup2(bq.w);
                FMA2(acc[ 0], A0.x, b0); FMA2(acc[ 1], A0.x, b1);
                FMA2(acc[ 2], A0.x, b2); FMA2(acc[ 3], A0.x, b3);
                FMA2(acc[ 4], A0.y, b0); FMA2(acc[ 5], A0.y, b1);
                FMA2(acc[ 6], A0.y, b2); FMA2(acc[ 7], A0.y, b3);
                FMA2(acc[ 8], A1.x, b0); FMA2(acc[ 9], A1.x, b1);
                FMA2(acc[10], A1.x, b2); FMA2(acc[11], A1.x, b3);
                FMA2(acc[12], A1.y, b0); FMA2(acc[13], A1.y, b1);
                FMA2(acc[14], A1.y, b2); FMA2(acc[15], A1.y, b3);
            }
        }

        // Epilogue: d = fl( fl(S_z + S_e) - 2*dot ), running first-index argmin.
        const int nb = nt * BN + (tx << 2);
#pragma unroll
        for (int j = 0; j < 4; j++) {
            float se = g_se[nb + j];
#pragma unroll
            for (int mp = 0; mp < 4; mp++) {
                unsigned long long p = acc[mp * 4 + j];
                float dlo = __uint_as_float((unsigned)(p & 0xffffffffu));
                float dhi = __uint_as_float((unsigned)(p >> 32));
                int m = mp * 2;
                float d0 = __fsub_rn(__fadd_rn(szr[m],     se), __fmul_rn(2.0f, dlo));
                float d1 = __fsub_rn(__fadd_rn(szr[m + 1], se), __fmul_rn(2.0f, dhi));
                if (d0 < bestd[m])     { bestd[m]     = d0; besti[m]     = nb + j; }
                if (d1 < bestd[m + 1]) { bestd[m + 1] = d1; besti[m + 1] = nb + j; }
            }
        }
    }

    // Cross-thread reduction: 16 tx partials per vector row, ties -> min index.
    __syncthreads();
    float* rv = smem;                        // [BM][16] floats
    int*   ri = (int*)(smem + BM * 16);      // [BM][16] ints
#pragma unroll
    for (int i = 0; i < 8; i++) {
        int m = (ty << 3) + i;
        rv[m * 16 + tx] = bestd[i];
        ri[m * 16 + tx] = besti[i];
    }
    __syncthreads();
    if (tid < BM) {
        float bv = rv[tid * 16];
        int   bi = ri[tid * 16];
#pragma unroll
        for (int t = 1; t < 16; t++) {
            float v  = rv[tid * 16 + t];
            int   ix = ri[tid * 16 + t];
            if (v < bv || (v == bv && ix < bi)) { bv = v; bi = ix; }
        }
        g_idx[m0 + tid] = bi;
    }
}

// ---------------------------------------------------------------------------
// Gather + straight-through + loss accumulation (+ indices as float).
// z_q = z + (e - z) with explicit fp32 ops to match the reference bitwise.
// ---------------------------------------------------------------------------
__global__ void gather_kernel(const float* __restrict__ z,
                              const float* __restrict__ cb,
                              float* __restrict__ out, int mode) {
    int v  = blockIdx.x * blockDim.x + threadIdx.x;  // 0..131071
    int b  = v >> 12;
    int hw = v & (HWN - 1);
    int idx = g_idx[v];
    const float4* crow = (const float4*)(cb + idx * CDIM);

    float lsum = 0.0f;
    for (int cc = 0; cc < CDIM / 8; cc++) {
        float4 e0 = crow[cc * 2];
        float4 e1 = crow[cc * 2 + 1];
        float er[8] = {e0.x, e0.y, e0.z, e0.w, e1.x, e1.y, e1.z, e1.w};
#pragma unroll
        for (int j = 0; j < 8; j++) {
            int c  = cc * 8 + j;
            size_t zi = (((size_t)b * CDIM + c) << 12) + hw;  // coalesced over hw
            float zv = z[zi];
            float t  = __fsub_rn(er[j], zv);          // e - z
            out[zi]  = __fadd_rn(zv, t);              // z + (e - z)
            lsum = __fmaf_rn(t, t, lsum);
        }
    }
    for (int o = 16; o > 0; o >>= 1)
        lsum += __shfl_down_sync(0xffffffffu, lsum, o);
    if ((threadIdx.x & 31) == 0) atomicAdd(&g_loss, (double)lsum);

    if (mode >= 2) out[N_ZQ + 2 + v] = (float)idx;
}

__global__ void finalize_kernel(float* __restrict__ out, int mode) {
    if (mode >= 1) {
        float mean = (float)(g_loss / (double)N_ZQ);
        out[N_ZQ]     = mean;          // codebook_loss
        out[N_ZQ + 1] = 0.25f * mean;  // commitment_loss = exactly 0.25 * mean
    }
}

// ---------------------------------------------------------------------------
extern "C" void kernel_launch(void* const* d_in, const int* in_sizes, int n_in,
                              void* d_out, int out_size) {
    const float* z  = (const float*)d_in[0];
    const float* cb = (const float*)d_in[1];
    float* out = (float*)d_out;

    int mode = 0;
    if (out_size >= N_ZQ + 2) mode = 1;
    if (out_size >= N_ZQ + 2 + N_VEC) mode = 2;

    const size_t SMEM = (size_t)(CDIM * BM + KC * BN) * sizeof(float); // 139264 B
    cudaFuncSetAttribute(vq_argmin_kernel,
                         cudaFuncAttributeMaxDynamicSharedMemorySize, (int)SMEM);

    prep_kernel<<<KCODES, 256>>>(cb);
    sz_kernel<<<N_VEC / 256, 256>>>(z);
    vq_argmin_kernel<<<N_VEC / BM, 256, SMEM>>>(z);
    gather_kernel<<<N_VEC / 256, 256>>>(z, cb, out, mode);
    finalize_kernel<<<1, 1>>>(out, mode);
}